// round 11
// baseline (speedup 1.0000x reference)
#include <cuda_runtime.h>
#include <cuda_fp16.h>
#include <math.h>

#define C 32
#define LAYERS 4
#define NFIX 2
#define MAXN 100000
#define MAXE 1600000
#define LC (LAYERS * C)   // 128
#define CAP 96            // per-node edge bucket capacity (deg ~ Poisson(16))
#define TILE 64           // nodes per mvtri block
#define ROWH 132          // accS row stride in halves

typedef unsigned long long u64;

// ---------------- device scratch (no runtime allocation allowed) -----------
// NOTE: g_cnt starts zero (static init) and every kernel_launch call leaves it
// zeroed (last mvtri re-zeros it) -> scatter can histogram without a zeroing
// launch, deterministically on every call.
__device__ __align__(256) __half g_dZ[(size_t)MAXN * LC];        // [N][L][C] fp16
__device__ __align__(256) __half g_acc[(size_t)MAXN * LC];       // [N][L][C] fp16
__device__ __align__(256) float  g_Z[(size_t)LAYERS * MAXN * C]; // [L][N][C]
__device__ __align__(16)  float  g_KT[LAYERS * C * C];           // [m][j][c]
__device__ __align__(16)  uint2  g_rec[(size_t)MAXN * CAP];      // (t, half2(w/2))
__device__ int g_cnt[MAXN];

// ---------------- helpers ---------------------------------------------------
__device__ __forceinline__ float silu_f(float x) {
    float t;
    asm("tanh.approx.f32 %0, %1;" : "=f"(t) : "f"(0.5f * x));
    float hx = 0.5f * x;
    return fmaf(hx, t, hx);
}
__device__ __forceinline__ u64 pack2(float a, float b) {
    u64 r; asm("mov.b64 %0, {%1, %2};" : "=l"(r) : "f"(a), "f"(b)); return r;
}
__device__ __forceinline__ void unpack2(u64 v, float& a, float& b) {
    asm("mov.b64 {%0, %1}, %2;" : "=f"(a), "=f"(b) : "l"(v));
}
__device__ __forceinline__ u64 fma2(u64 a, u64 b, u64 c) {
    u64 d; asm("fma.rn.f32x2 %0, %1, %2, %3;" : "=l"(d) : "l"(a), "l"(b), "l"(c));
    return d;
}
__device__ __forceinline__ u64 add2(u64 a, u64 b) {
    u64 d; asm("add.rn.f32x2 %0, %1, %2;" : "=l"(d) : "l"(a), "l"(b));
    return d;
}
__device__ __forceinline__ __half2 htanh2(__half2 x) {
    unsigned r, xi = *(unsigned*)&x;
    asm("tanh.approx.f16x2 %0, %1;" : "=r"(r) : "r"(xi));
    return *(__half2*)&r;
}

// ---------------- setup: scatter (+ folded KT transpose) --------------------
__global__ void scatter_kt_kernel(const int* __restrict__ ei,
                                  const float* __restrict__ ew,
                                  int* cnt, uint2* rec,
                                  const float* __restrict__ K, float* __restrict__ KT,
                                  int E, int edgeBlks) {
    if ((int)blockIdx.x >= edgeBlks) {
        // KT[m][j][c] = K[m][c][j]
        int i = (blockIdx.x - edgeBlks) * 256 + threadIdx.x;
        if (i < LAYERS * C * C) {
            int m = i >> 10;
            int c = (i >> 5) & 31;
            int j = i & 31;
            KT[m * C * C + j * C + c] = K[i];
        }
        return;
    }
    int e = blockIdx.x * 256 + threadIdx.x;
    if (e >= E) return;
    int s = __ldg(ei + e);
    int t = __ldg(ei + E + e);
    float w = __ldg(ew + e);
    __half2 hw = __float2half2_rn(0.5f * w);
    int p = atomicAdd(&cnt[s], 1);
    if (p < CAP) rec[(size_t)s * CAP + p] = make_uint2((unsigned)t, *(unsigned*)&hw);
}

// ---------------------------------------------------------------------------
// Node forward: 2 nodes/thread, h computed in two 16-channel chunks so the
// full h[32] never lives alongside the 32-channel d accumulators (no spills).
// ---------------------------------------------------------------------------
__global__ __launch_bounds__(256, 2) void node_forward_kernel(
        const float* __restrict__ Z,
        const float* __restrict__ f,
        const float* __restrict__ Kf,
        const float* __restrict__ K,
        __half* __restrict__ dZ,
        int N, int useZ)
{
    __shared__ __align__(16) float Kfs[2 * C * C];   // 8 KB
    __shared__ __align__(16) float Ks[C * C];        // 4 KB
    const int l = blockIdx.y;
    {
        const float4* Kfl = (const float4*)(Kf + (size_t)l * 2 * C * C);
        const float4* Kl  = (const float4*)(K  + (size_t)l * C * C);
        float4* s0 = (float4*)Kfs;
        float4* s1 = (float4*)Ks;
        for (int i = threadIdx.x; i < 2 * C * C / 4; i += blockDim.x) s0[i] = Kfl[i];
        for (int i = threadIdx.x; i < C * C / 4;     i += blockDim.x) s1[i] = Kl[i];
    }
    __syncthreads();

    const int n0 = blockIdx.x * 512 + threadIdx.x;
    const int n1 = n0 + 256;
    if (n0 >= N) return;
    const bool v1 = (n1 < N);

    u64 dp0[16], dp1[16];   // full 32 output channels per node
#pragma unroll
    for (int i = 0; i < 16; i++) { dp0[i] = 0ULL; dp1[i] = 0ULL; }

#pragma unroll
    for (int chunk = 0; chunk < 2; chunk++) {
        u64 hp0[8], hp1[8];   // 16 h-channels per node
#pragma unroll
        for (int i = 0; i < 8; i++) { hp0[i] = 0ULL; hp1[i] = 0ULL; }

        if (useZ) {
            const float4* z0r = (const float4*)(Z + ((size_t)l * N + n0) * C);
            const float4* z1r = (const float4*)(Z + ((size_t)l * N + n1) * C);
#pragma unroll
            for (int k4 = 0; k4 < 8; k4++) {
                float4 a = z0r[k4];
                float4 b = v1 ? z1r[k4] : make_float4(0.f, 0.f, 0.f, 0.f);
                float as[4] = {a.x, a.y, a.z, a.w};
                float bs[4] = {b.x, b.y, b.z, b.w};
#pragma unroll
                for (int kk = 0; kk < 4; kk++) {
                    u64 s0 = pack2(as[kk], as[kk]);
                    u64 s1 = pack2(bs[kk], bs[kk]);
                    const ulonglong2* wr =
                        (const ulonglong2*)&Kfs[(k4 * 4 + kk) * C + chunk * 16];
#pragma unroll
                    for (int c4 = 0; c4 < 4; c4++) {
                        ulonglong2 w = wr[c4];
                        hp0[2 * c4 + 0] = fma2(s0, w.x, hp0[2 * c4 + 0]);
                        hp0[2 * c4 + 1] = fma2(s0, w.y, hp0[2 * c4 + 1]);
                        hp1[2 * c4 + 0] = fma2(s1, w.x, hp1[2 * c4 + 0]);
                        hp1[2 * c4 + 1] = fma2(s1, w.y, hp1[2 * c4 + 1]);
                    }
                }
            }
        }
        {
            const float4* f0r = (const float4*)(f + (size_t)n0 * C);
            const float4* f1r = (const float4*)(f + (size_t)n1 * C);
#pragma unroll
            for (int k4 = 0; k4 < 8; k4++) {
                float4 a = f0r[k4];
                float4 b = v1 ? f1r[k4] : make_float4(0.f, 0.f, 0.f, 0.f);
                float as[4] = {a.x, a.y, a.z, a.w};
                float bs[4] = {b.x, b.y, b.z, b.w};
#pragma unroll
                for (int kk = 0; kk < 4; kk++) {
                    u64 s0 = pack2(as[kk], as[kk]);
                    u64 s1 = pack2(bs[kk], bs[kk]);
                    const ulonglong2* wr =
                        (const ulonglong2*)&Kfs[(C + k4 * 4 + kk) * C + chunk * 16];
#pragma unroll
                    for (int c4 = 0; c4 < 4; c4++) {
                        ulonglong2 w = wr[c4];
                        hp0[2 * c4 + 0] = fma2(s0, w.x, hp0[2 * c4 + 0]);
                        hp0[2 * c4 + 1] = fma2(s0, w.y, hp0[2 * c4 + 1]);
                        hp1[2 * c4 + 0] = fma2(s1, w.x, hp1[2 * c4 + 0]);
                        hp1[2 * c4 + 1] = fma2(s1, w.y, hp1[2 * c4 + 1]);
                    }
                }
            }
        }

        float h0c[16], h1c[16];
#pragma unroll
        for (int i = 0; i < 8; i++) {
            unpack2(hp0[i], h0c[2 * i], h0c[2 * i + 1]);
            unpack2(hp1[i], h1c[2 * i], h1c[2 * i + 1]);
        }
#pragma unroll
        for (int c = 0; c < 16; c++) { h0c[c] = silu_f(h0c[c]); h1c[c] = silu_f(h1c[c]); }

        // accumulate this h-chunk's contribution to all 32 output channels
#pragma unroll
        for (int kk = 0; kk < 16; kk++) {
            const int k = chunk * 16 + kk;
            u64 s0 = pack2(h0c[kk], h0c[kk]);
            u64 s1 = pack2(h1c[kk], h1c[kk]);
            const ulonglong2* wr = (const ulonglong2*)&Ks[k * C];
#pragma unroll
            for (int c4 = 0; c4 < 8; c4++) {
                ulonglong2 w = wr[c4];
                dp0[2 * c4 + 0] = fma2(s0, w.x, dp0[2 * c4 + 0]);
                dp0[2 * c4 + 1] = fma2(s0, w.y, dp0[2 * c4 + 1]);
                dp1[2 * c4 + 0] = fma2(s1, w.x, dp1[2 * c4 + 0]);
                dp1[2 * c4 + 1] = fma2(s1, w.y, dp1[2 * c4 + 1]);
            }
        }
    }

    union { __half2 h2[16]; uint4 u[4]; } p0, p1;
#pragma unroll
    for (int i = 0; i < 16; i++) {
        float x, y;
        unpack2(dp0[i], x, y);
        p0.h2[i] = __float22half2_rn(make_float2(x, y));
        unpack2(dp1[i], x, y);
        p1.h2[i] = __float22half2_rn(make_float2(x, y));
    }
    uint4* dz0 = (uint4*)(dZ + ((size_t)n0 * LAYERS + l) * C);
    uint4* dz1 = (uint4*)(dZ + ((size_t)n1 * LAYERS + l) * C);
#pragma unroll
    for (int q = 0; q < 4; q++) {
        dz0[q] = p0.u[q];
        if (v1) dz1[q] = p1.u[q];
    }
}

// ---------------------------------------------------------------------------
// Edge gather: 2 nodes/warp (16 lanes each). CSR records for 16 edges loaded
// with ONE coalesced 128B LDG per half, distributed by shfl; all dZ gathers
// independent. silu in fp16x2 (w/2 pre-packed as half2 in rec).
// ---------------------------------------------------------------------------
__device__ __forceinline__ void edge_accum4(uint4 zb,
                                            __half2 a0, __half2 a1, __half2 a2, __half2 a3,
                                            unsigned wbits, bool en, u64* acc)
{
    __half2 wh = *(__half2*)&wbits;
    __half2 b0 = *(__half2*)&zb.x;
    __half2 b1 = *(__half2*)&zb.y;
    __half2 b2 = *(__half2*)&zb.z;
    __half2 b3 = *(__half2*)&zb.w;
    __half2 hx0 = __hmul2(wh, __hsub2(a0, b0));
    __half2 hx1 = __hmul2(wh, __hsub2(a1, b1));
    __half2 hx2 = __hmul2(wh, __hsub2(a2, b2));
    __half2 hx3 = __hmul2(wh, __hsub2(a3, b3));
    __half2 t0 = htanh2(hx0);
    __half2 t1 = htanh2(hx1);
    __half2 t2 = htanh2(hx2);
    __half2 t3 = htanh2(hx3);
    __half2 g0 = __hfma2(hx0, t0, hx0);
    __half2 g1 = __hfma2(hx1, t1, hx1);
    __half2 g2 = __hfma2(hx2, t2, hx2);
    __half2 g3 = __hfma2(hx3, t3, hx3);
    float2 f0 = __half22float2(g0);
    float2 f1 = __half22float2(g1);
    float2 f2 = __half22float2(g2);
    float2 f3 = __half22float2(g3);
    if (en) {
        acc[0] = add2(acc[0], pack2(f0.x, f0.y));
        acc[1] = add2(acc[1], pack2(f1.x, f1.y));
        acc[2] = add2(acc[2], pack2(f2.x, f2.y));
        acc[3] = add2(acc[3], pack2(f3.x, f3.y));
    }
}

__global__ __launch_bounds__(256, 6) void edge_gather_kernel(
        const __half* __restrict__ dZ,
        const uint2* __restrict__ rec,
        const int* __restrict__ cnt,
        __half* __restrict__ acc,
        int N)
{
    const int lane = threadIdx.x & 31;
    const int warp = threadIdx.x >> 5;
    const int hbase = lane & 16;         // shfl base for this half
    const int sub   = lane & 15;         // lane within node (owns 8 halves)
    const int gwarp = blockIdx.x * 8 + warp;
    const int nwarps = gridDim.x * 8;

    for (int nb = gwarp * 2; nb < N; nb += nwarps * 2) {
        const int n = nb + (lane >> 4);
        const bool valid = (n < N);
        const int nc = valid ? n : (N - 1);

        uint4 za = __ldg((const uint4*)(dZ + (size_t)nc * LC) + sub);
        __half2 a0 = *(__half2*)&za.x;
        __half2 a1 = *(__half2*)&za.y;
        __half2 a2 = *(__half2*)&za.z;
        __half2 a3 = *(__half2*)&za.w;

        u64 accv[4] = {0ULL, 0ULL, 0ULL, 0ULL};
        int deg = valid ? __ldg(cnt + nc) : 0;
        if (deg > CAP) deg = CAP;
        // warp-uniform loop bound (max of the two halves)
        int dboth = max(deg, __shfl_xor_sync(0xffffffffu, deg, 16));
        const uint2* row = rec + (size_t)nc * CAP;

        for (int base = 0; base < dboth; base += 16) {
            // one coalesced 128B load per half fetches 16 records
            uint2 rc = __ldg(row + base + sub);   // base+sub <= 95 < CAP: safe
            const int cmax = min(16, dboth - base);
            for (int k = 0; k < cmax; k += 4) {
#pragma unroll
                for (int i = 0; i < 4; i++) {
                    const int kk = k + i;
                    unsigned t = __shfl_sync(0xffffffffu, rc.x, hbase | kk);
                    unsigned w = __shfl_sync(0xffffffffu, rc.y, hbase | kk);
                    uint4 z = __ldg((const uint4*)(dZ + (size_t)t * LC) + sub);
                    edge_accum4(z, a0, a1, a2, a3, w,
                                (base + kk) < deg, accv);
                }
            }
        }

        if (valid) {
            float x, y;
            uint4 packed;
            unpack2(accv[0], x, y);
            *(__half2*)&packed.x = __float22half2_rn(make_float2(x, y));
            unpack2(accv[1], x, y);
            *(__half2*)&packed.y = __float22half2_rn(make_float2(x, y));
            unpack2(accv[2], x, y);
            *(__half2*)&packed.z = __float22half2_rn(make_float2(x, y));
            unpack2(accv[3], x, y);
            *(__half2*)&packed.w = __float22half2_rn(make_float2(x, y));
            *(uint4*)(acc + (size_t)n * LC + sub * 8) = packed;
        }
    }
}

// ---------------------------------------------------------------------------
// mvtri: per 64-node tile: KT + acc tile -> SMEM; matvec thread-per-(node,m)
// with warp-uniform KT broadcast; tridiag warp-per-node -> Z global.
// Last invocation also re-zeros cnt for the next kernel_launch call.
// ---------------------------------------------------------------------------
__global__ __launch_bounds__(256) void mvtri_kernel(
        const __half* __restrict__ acc,
        const float* __restrict__ KTg,
        const float* __restrict__ X,
        float* __restrict__ Zout,
        float* __restrict__ lastOut,
        int* cntZero,
        int N)
{
    __shared__ __align__(16) float KTs[LAYERS * C * C];   // 16 KB
    __shared__ __align__(8)  __half accS[TILE * ROWH];    // 16.9 KB

    if (cntZero) {
        int gid = blockIdx.x * blockDim.x + threadIdx.x;
        if (gid < N) cntZero[gid] = 0;
    }

    {
        const float4* src = (const float4*)KTg;
        float4* dst = (float4*)KTs;
        for (int i = threadIdx.x; i < LAYERS * C * C / 4; i += blockDim.x)
            dst[i] = src[i];
    }
    const int tileBase = blockIdx.x * TILE;
    for (int idx = threadIdx.x; idx < TILE * 32; idx += blockDim.x) {
        int nn = idx >> 5;
        int u  = idx & 31;
        int gn = tileBase + nn;
        if (gn < N)
            *(uint2*)&accS[nn * ROWH + u * 4] =
                __ldg((const uint2*)(acc + (size_t)gn * LC) + u);
    }
    __syncthreads();

    {
        const int m  = threadIdx.x >> 6;
        const int ln = threadIdx.x & 63;
        if (tileBase + ln < N) {
            __half* seg = &accS[ln * ROWH + m * C];
            u64 yp[16];
#pragma unroll
            for (int i = 0; i < 16; i++) yp[i] = 0ULL;
#pragma unroll
            for (int j = 0; j < C; j++) {
                float aj = __half2float(seg[j]);
                u64 a2 = pack2(aj, aj);
                const ulonglong2* wr = (const ulonglong2*)&KTs[(m * C + j) * C];
#pragma unroll
                for (int c4 = 0; c4 < 8; c4++) {
                    ulonglong2 w = wr[c4];
                    yp[2 * c4 + 0] = fma2(a2, w.x, yp[2 * c4 + 0]);
                    yp[2 * c4 + 1] = fma2(a2, w.y, yp[2 * c4 + 1]);
                }
            }
#pragma unroll
            for (int i = 0; i < 16; i++) {
                float x, y;
                unpack2(yp[i], x, y);
                *(__half2*)(seg + 2 * i) = __float22half2_rn(make_float2(-x, -y));
            }
        }
    }
    __syncthreads();

    const int lane = threadIdx.x & 31;
    const int warp = threadIdx.x >> 5;
    const size_t NC = (size_t)N * C;
#pragma unroll 1
    for (int k = 0; k < 8; k++) {
        const int idx = warp * 8 + k;
        const int n = tileBase + idx;
        if (n >= N) continue;
        const __half* rowp = &accS[idx * ROWH];
        float Y0 = __half2float(rowp[0 * C + lane]);
        float Y1 = __half2float(rowp[1 * C + lane]);
        float Y2 = __half2float(rowp[2 * C + lane]);
        float Y3 = __half2float(rowp[3 * C + lane]) + __ldg(X + (size_t)n * C + lane);

        const float s12 = 0.70710678118654752f;
        const float s23 = 0.81649658092772603f;
        const float s34 = 0.86602540378443865f;
        const float s45 = 0.89442719099991588f;
        float t0 = s12 * Y0;
        float t1 = s23 * (s12 * t0 + Y1);
        float t2 = s34 * (s23 * t1 + Y2);
        float t3 = s45 * (s34 * t2 + Y3);
        float w3 = s45 * t3;
        float w2 = s34 * (s34 * w3 + t2);
        float w1 = s23 * (s23 * w2 + t1);
        float w0 = s12 * (s12 * w1 + t0);

        const size_t base = (size_t)n * C + lane;
        Zout[0 * NC + base] = w0;
        Zout[1 * NC + base] = w1;
        Zout[2 * NC + base] = w2;
        Zout[3 * NC + base] = w3;
        if (lastOut) lastOut[base] = w3;
    }
}

// ---------------------------------------------------------------------------
extern "C" void kernel_launch(void* const* d_in, const int* in_sizes, int n_in,
                              void* d_out, int out_size)
{
    const float* X  = (const float*)d_in[0];
    const float* f  = (const float*)d_in[1];
    const int*   ei = (const int*)d_in[2];
    const float* ew = (const float*)d_in[3];
    const float* K  = (const float*)d_in[4];
    const float* Kf = (const float*)d_in[5];

    const int N = in_sizes[0] / C;
    const int E = in_sizes[3];

    __half *dZ, *acc; float *Zb, *KT; uint2* rec; int* cnt;
    cudaGetSymbolAddress((void**)&dZ,  g_dZ);
    cudaGetSymbolAddress((void**)&acc, g_acc);
    cudaGetSymbolAddress((void**)&Zb,  g_Z);
    cudaGetSymbolAddress((void**)&KT,  g_KT);
    cudaGetSymbolAddress((void**)&rec, g_rec);
    cudaGetSymbolAddress((void**)&cnt, g_cnt);

    const size_t NC = (size_t)N * C;
    float* out = (float*)d_out;
    float* Zfinal;
    float* lastPtr;
    if ((size_t)out_size >= (size_t)(LAYERS + 1) * NC) {
        lastPtr = out;            // Z[-1] first
        Zfinal  = out + NC;       // then full Z
    } else if ((size_t)out_size >= (size_t)LAYERS * NC) {
        Zfinal  = out;
        lastPtr = nullptr;
    } else {
        Zfinal  = Zb;
        lastPtr = out;
    }

    const int edgeBlks = (E + 255) / 256;
    scatter_kt_kernel<<<edgeBlks + 16, 256>>>(ei, ew, cnt, rec, K, KT, E, edgeBlks);

    dim3 nodeGrid((N + 511) / 512, LAYERS);
    const int gatherBlocks = 888;                 // 6 per SM, 8 warps each
    const int mvtriBlocks = (N + TILE - 1) / TILE;

    for (int it = 0; it < NFIX; it++) {
        node_forward_kernel<<<nodeGrid, 256>>>(Zb, f, Kf, K, dZ, N, it > 0 ? 1 : 0);
        edge_gather_kernel<<<gatherBlocks, 256>>>(dZ, rec, cnt, acc, N);
        const bool last = (it == NFIX - 1);
        mvtri_kernel<<<mvtriBlocks, 256>>>(acc, KT, X,
                                           last ? Zfinal : Zb,
                                           last ? lastPtr : nullptr,
                                           last ? cnt : nullptr,
                                           N);
    }
}

// round 12
// speedup vs baseline: 1.1210x; 1.1210x over previous
#include <cuda_runtime.h>
#include <cuda_fp16.h>
#include <math.h>

#define C 32
#define LAYERS 4
#define NFIX 2
#define MAXN 100000
#define MAXE 1600000
#define LC (LAYERS * C)   // 128
#define CAP 96            // per-node edge bucket capacity (deg ~ Poisson(16))
#define TILE 64           // nodes per mvtri tile
#define ROWH 132          // accS row stride in halves

typedef unsigned long long u64;

// ---------------- device scratch (no runtime allocation allowed) -----------
// g_cnt starts zero (static init); every kernel_launch call leaves it zeroed
// (last mvtri re-zeros it), so scatter can histogram without a zeroing launch.
__device__ __align__(256) __half g_dZ[(size_t)MAXN * LC];        // [N][L][C] fp16
__device__ __align__(256) __half g_acc[(size_t)MAXN * LC];       // [N][L][C] fp16
__device__ __align__(256) float  g_Z[(size_t)LAYERS * MAXN * C]; // [L][N][C]
__device__ __align__(16)  float  g_KT[LAYERS * C * C];           // [m][j][c]
__device__ __align__(16)  uint2  g_rec[(size_t)MAXN * CAP];      // (t, w fp32)
__device__ int g_cnt[MAXN];

// ---------------- helpers ---------------------------------------------------
__device__ __forceinline__ float silu_f(float x) {
    float t;
    asm("tanh.approx.f32 %0, %1;" : "=f"(t) : "f"(0.5f * x));
    float hx = 0.5f * x;
    return fmaf(hx, t, hx);
}
__device__ __forceinline__ u64 pack2(float a, float b) {
    u64 r; asm("mov.b64 %0, {%1, %2};" : "=l"(r) : "f"(a), "f"(b)); return r;
}
__device__ __forceinline__ void unpack2(u64 v, float& a, float& b) {
    asm("mov.b64 {%0, %1}, %2;" : "=f"(a), "=f"(b) : "l"(v));
}
__device__ __forceinline__ u64 fma2(u64 a, u64 b, u64 c) {
    u64 d; asm("fma.rn.f32x2 %0, %1, %2, %3;" : "=l"(d) : "l"(a), "l"(b), "l"(c));
    return d;
}
__device__ __forceinline__ u64 add2(u64 a, u64 b) {
    u64 d; asm("add.rn.f32x2 %0, %1, %2;" : "=l"(d) : "l"(a), "l"(b));
    return d;
}
__device__ __forceinline__ __half2 htanh2(__half2 x) {
    unsigned r, xi = *(unsigned*)&x;
    asm("tanh.approx.f16x2 %0, %1;" : "=r"(r) : "r"(xi));
    return *(__half2*)&r;
}

// ---------------- setup: scatter (+ folded KT transpose) --------------------
__global__ void scatter_kt_kernel(const int* __restrict__ ei,
                                  const float* __restrict__ ew,
                                  int* cnt, uint2* rec,
                                  const float* __restrict__ K, float* __restrict__ KT,
                                  int E, int edgeBlks) {
    if ((int)blockIdx.x >= edgeBlks) {
        int i = (blockIdx.x - edgeBlks) * 256 + threadIdx.x;
        if (i < LAYERS * C * C) {
            int m = i >> 10;
            int c = (i >> 5) & 31;
            int j = i & 31;
            KT[m * C * C + j * C + c] = K[i];
        }
        return;
    }
    int e = blockIdx.x * 256 + threadIdx.x;
    if (e >= E) return;
    int s = __ldg(ei + e);
    int t = __ldg(ei + E + e);
    float w = __ldg(ew + e);
    int p = atomicAdd(&cnt[s], 1);
    if (p < CAP) rec[(size_t)s * CAP + p] = make_uint2((unsigned)t, __float_as_uint(w));
}

// ---------------------------------------------------------------------------
// Node forward (R10 version, measured 57.7us): 2 nodes/thread, 128-reg cap.
// ---------------------------------------------------------------------------
__global__ __launch_bounds__(256, 2) void node_forward_kernel(
        const float* __restrict__ Z,
        const float* __restrict__ f,
        const float* __restrict__ Kf,
        const float* __restrict__ K,
        __half* __restrict__ dZ,
        int N, int useZ)
{
    __shared__ __align__(16) float Kfs[2 * C * C];   // 8 KB
    __shared__ __align__(16) float Ks[C * C];        // 4 KB
    const int l = blockIdx.y;
    {
        const float4* Kfl = (const float4*)(Kf + (size_t)l * 2 * C * C);
        const float4* Kl  = (const float4*)(K  + (size_t)l * C * C);
        float4* s0 = (float4*)Kfs;
        float4* s1 = (float4*)Ks;
        for (int i = threadIdx.x; i < 2 * C * C / 4; i += blockDim.x) s0[i] = Kfl[i];
        for (int i = threadIdx.x; i < C * C / 4;     i += blockDim.x) s1[i] = Kl[i];
    }
    __syncthreads();

    const int n0 = blockIdx.x * 512 + threadIdx.x;
    const int n1 = n0 + 256;
    if (n0 >= N) return;
    const bool v1 = (n1 < N);

    u64 hp0[16], hp1[16];
#pragma unroll
    for (int i = 0; i < 16; i++) { hp0[i] = 0ULL; hp1[i] = 0ULL; }

    if (useZ) {
        const float4* z0r = (const float4*)(Z + ((size_t)l * N + n0) * C);
        const float4* z1r = (const float4*)(Z + ((size_t)l * N + n1) * C);
#pragma unroll
        for (int k4 = 0; k4 < 8; k4++) {
            float4 a = z0r[k4];
            float4 b = v1 ? z1r[k4] : make_float4(0.f, 0.f, 0.f, 0.f);
            float as[4] = {a.x, a.y, a.z, a.w};
            float bs[4] = {b.x, b.y, b.z, b.w};
#pragma unroll
            for (int kk = 0; kk < 4; kk++) {
                u64 s0 = pack2(as[kk], as[kk]);
                u64 s1 = pack2(bs[kk], bs[kk]);
                const ulonglong2* wr = (const ulonglong2*)&Kfs[(k4 * 4 + kk) * C];
#pragma unroll
                for (int c4 = 0; c4 < 8; c4++) {
                    ulonglong2 w = wr[c4];
                    hp0[2 * c4 + 0] = fma2(s0, w.x, hp0[2 * c4 + 0]);
                    hp0[2 * c4 + 1] = fma2(s0, w.y, hp0[2 * c4 + 1]);
                    hp1[2 * c4 + 0] = fma2(s1, w.x, hp1[2 * c4 + 0]);
                    hp1[2 * c4 + 1] = fma2(s1, w.y, hp1[2 * c4 + 1]);
                }
            }
        }
    }
    {
        const float4* f0r = (const float4*)(f + (size_t)n0 * C);
        const float4* f1r = (const float4*)(f + (size_t)n1 * C);
#pragma unroll
        for (int k4 = 0; k4 < 8; k4++) {
            float4 a = f0r[k4];
            float4 b = v1 ? f1r[k4] : make_float4(0.f, 0.f, 0.f, 0.f);
            float as[4] = {a.x, a.y, a.z, a.w};
            float bs[4] = {b.x, b.y, b.z, b.w};
#pragma unroll
            for (int kk = 0; kk < 4; kk++) {
                u64 s0 = pack2(as[kk], as[kk]);
                u64 s1 = pack2(bs[kk], bs[kk]);
                const ulonglong2* wr = (const ulonglong2*)&Kfs[(C + k4 * 4 + kk) * C];
#pragma unroll
                for (int c4 = 0; c4 < 8; c4++) {
                    ulonglong2 w = wr[c4];
                    hp0[2 * c4 + 0] = fma2(s0, w.x, hp0[2 * c4 + 0]);
                    hp0[2 * c4 + 1] = fma2(s0, w.y, hp0[2 * c4 + 1]);
                    hp1[2 * c4 + 0] = fma2(s1, w.x, hp1[2 * c4 + 0]);
                    hp1[2 * c4 + 1] = fma2(s1, w.y, hp1[2 * c4 + 1]);
                }
            }
        }
    }

    float h0[C], h1[C];
#pragma unroll
    for (int i = 0; i < 16; i++) {
        unpack2(hp0[i], h0[2 * i], h0[2 * i + 1]);
        unpack2(hp1[i], h1[2 * i], h1[2 * i + 1]);
    }
#pragma unroll
    for (int c = 0; c < C; c++) { h0[c] = silu_f(h0[c]); h1[c] = silu_f(h1[c]); }

    __half* dz0 = dZ + ((size_t)n0 * LAYERS + l) * C;
    __half* dz1 = dZ + ((size_t)n1 * LAYERS + l) * C;
#pragma unroll
    for (int hf = 0; hf < 2; hf++) {
        u64 dp0[8], dp1[8];
#pragma unroll
        for (int i = 0; i < 8; i++) { dp0[i] = 0ULL; dp1[i] = 0ULL; }
#pragma unroll
        for (int k = 0; k < C; k++) {
            u64 s0 = pack2(h0[k], h0[k]);
            u64 s1 = pack2(h1[k], h1[k]);
            const ulonglong2* wr = (const ulonglong2*)&Ks[k * C + hf * 16];
#pragma unroll
            for (int c4 = 0; c4 < 4; c4++) {
                ulonglong2 w = wr[c4];
                dp0[2 * c4 + 0] = fma2(s0, w.x, dp0[2 * c4 + 0]);
                dp0[2 * c4 + 1] = fma2(s0, w.y, dp0[2 * c4 + 1]);
                dp1[2 * c4 + 0] = fma2(s1, w.x, dp1[2 * c4 + 0]);
                dp1[2 * c4 + 1] = fma2(s1, w.y, dp1[2 * c4 + 1]);
            }
        }
        union { __half2 h2[8]; uint4 u[2]; } p0, p1;
#pragma unroll
        for (int i = 0; i < 8; i++) {
            float x, y;
            unpack2(dp0[i], x, y);
            p0.h2[i] = __float22half2_rn(make_float2(x, y));
            unpack2(dp1[i], x, y);
            p1.h2[i] = __float22half2_rn(make_float2(x, y));
        }
        ((uint4*)dz0)[hf * 2 + 0] = p0.u[0];
        ((uint4*)dz0)[hf * 2 + 1] = p0.u[1];
        if (v1) {
            ((uint4*)dz1)[hf * 2 + 0] = p1.u[0];
            ((uint4*)dz1)[hf * 2 + 1] = p1.u[1];
        }
    }
}

// ---------------------------------------------------------------------------
// Edge gather (R10 version): 2 nodes/warp (16 lanes each, uint4/lane),
// per-half deg loop, fp16x2 silu, f32x2 accumulate.
// ---------------------------------------------------------------------------
__device__ __forceinline__ void edge_accum4(uint4 zb,
                                            __half2 a0, __half2 a1, __half2 a2, __half2 a3,
                                            __half2 wh, u64* acc)
{
    __half2 b0 = *(__half2*)&zb.x;
    __half2 b1 = *(__half2*)&zb.y;
    __half2 b2 = *(__half2*)&zb.z;
    __half2 b3 = *(__half2*)&zb.w;
    __half2 hx0 = __hmul2(wh, __hsub2(a0, b0));
    __half2 hx1 = __hmul2(wh, __hsub2(a1, b1));
    __half2 hx2 = __hmul2(wh, __hsub2(a2, b2));
    __half2 hx3 = __hmul2(wh, __hsub2(a3, b3));
    __half2 t0 = htanh2(hx0);
    __half2 t1 = htanh2(hx1);
    __half2 t2 = htanh2(hx2);
    __half2 t3 = htanh2(hx3);
    __half2 g0 = __hfma2(hx0, t0, hx0);
    __half2 g1 = __hfma2(hx1, t1, hx1);
    __half2 g2 = __hfma2(hx2, t2, hx2);
    __half2 g3 = __hfma2(hx3, t3, hx3);
    float2 f0 = __half22float2(g0);
    float2 f1 = __half22float2(g1);
    float2 f2 = __half22float2(g2);
    float2 f3 = __half22float2(g3);
    acc[0] = add2(acc[0], pack2(f0.x, f0.y));
    acc[1] = add2(acc[1], pack2(f1.x, f1.y));
    acc[2] = add2(acc[2], pack2(f2.x, f2.y));
    acc[3] = add2(acc[3], pack2(f3.x, f3.y));
}

__global__ __launch_bounds__(256, 6) void edge_gather_kernel(
        const __half* __restrict__ dZ,
        const uint2* __restrict__ rec,
        const int* __restrict__ cnt,
        __half* __restrict__ acc,
        int N)
{
    const int lane = threadIdx.x & 31;
    const int warp = threadIdx.x >> 5;
    const int half = lane >> 4;
    const int sub  = lane & 15;
    const int gwarp = blockIdx.x * 8 + warp;
    const int nwarps = gridDim.x * 8;

    for (int nb = gwarp * 2; nb < N; nb += nwarps * 2) {
        const int n = nb + half;
        const bool valid = (n < N);
        const int nc = valid ? n : (N - 1);

        uint4 za = __ldg((const uint4*)(dZ + (size_t)nc * LC) + sub);
        __half2 a0 = *(__half2*)&za.x;
        __half2 a1 = *(__half2*)&za.y;
        __half2 a2 = *(__half2*)&za.z;
        __half2 a3 = *(__half2*)&za.w;

        u64 accv[4] = {0ULL, 0ULL, 0ULL, 0ULL};
        int deg = valid ? __ldg(cnt + nc) : 0;
        if (deg > CAP) deg = CAP;
        const uint2* row = rec + (size_t)nc * CAP;

        int p = 0;
        for (; p + 4 <= deg; p += 4) {
            uint2 r0 = __ldg(row + p + 0);
            uint2 r1 = __ldg(row + p + 1);
            uint2 r2 = __ldg(row + p + 2);
            uint2 r3 = __ldg(row + p + 3);
            uint4 z0 = __ldg((const uint4*)(dZ + (size_t)r0.x * LC) + sub);
            uint4 z1 = __ldg((const uint4*)(dZ + (size_t)r1.x * LC) + sub);
            uint4 z2 = __ldg((const uint4*)(dZ + (size_t)r2.x * LC) + sub);
            uint4 z3 = __ldg((const uint4*)(dZ + (size_t)r3.x * LC) + sub);
            edge_accum4(z0, a0, a1, a2, a3, __float2half2_rn(0.5f * __uint_as_float(r0.y)), accv);
            edge_accum4(z1, a0, a1, a2, a3, __float2half2_rn(0.5f * __uint_as_float(r1.y)), accv);
            edge_accum4(z2, a0, a1, a2, a3, __float2half2_rn(0.5f * __uint_as_float(r2.y)), accv);
            edge_accum4(z3, a0, a1, a2, a3, __float2half2_rn(0.5f * __uint_as_float(r3.y)), accv);
        }
        for (; p < deg; p++) {
            uint2 r0 = __ldg(row + p);
            uint4 z0 = __ldg((const uint4*)(dZ + (size_t)r0.x * LC) + sub);
            edge_accum4(z0, a0, a1, a2, a3, __float2half2_rn(0.5f * __uint_as_float(r0.y)), accv);
        }

        if (valid) {
            float x, y;
            uint4 packed;
            unpack2(accv[0], x, y);
            *(__half2*)&packed.x = __float22half2_rn(make_float2(x, y));
            unpack2(accv[1], x, y);
            *(__half2*)&packed.y = __float22half2_rn(make_float2(x, y));
            unpack2(accv[2], x, y);
            *(__half2*)&packed.z = __float22half2_rn(make_float2(x, y));
            unpack2(accv[3], x, y);
            *(__half2*)&packed.w = __float22half2_rn(make_float2(x, y));
            *(uint4*)(acc + (size_t)n * LC + sub * 8) = packed;
        }
    }
}

// ---------------------------------------------------------------------------
// mvtri: grid-stride over 64-node tiles; KT loaded ONCE per block; 4 CTAs/SM.
// matvec thread-per-(node,m) with warp-uniform KT broadcast; tridiag from SMEM.
// Last invocation also re-zeros cnt.
// ---------------------------------------------------------------------------
__global__ __launch_bounds__(256, 4) void mvtri_kernel(
        const __half* __restrict__ acc,
        const float* __restrict__ KTg,
        const float* __restrict__ X,
        float* __restrict__ Zout,
        float* __restrict__ lastOut,
        int* cntZero,
        int N)
{
    __shared__ __align__(16) float KTs[LAYERS * C * C];   // 16 KB
    __shared__ __align__(8)  __half accS[TILE * ROWH];    // 16.9 KB

    if (cntZero) {
        for (int i = blockIdx.x * 256 + threadIdx.x; i < N; i += gridDim.x * 256)
            cntZero[i] = 0;
    }

    // KT loaded once per block (coalesced)
    {
        const float4* src = (const float4*)KTg;
        float4* dst = (float4*)KTs;
        for (int i = threadIdx.x; i < LAYERS * C * C / 4; i += blockDim.x)
            dst[i] = src[i];
    }

    const int numTiles = (N + TILE - 1) / TILE;
    const int lane = threadIdx.x & 31;
    const int warp = threadIdx.x >> 5;
    const size_t NC = (size_t)N * C;

    for (int tile = blockIdx.x; tile < numTiles; tile += gridDim.x) {
        const int tileBase = tile * TILE;

        __syncthreads();   // KT ready (first iter) / accS free (later iters)

        for (int idx = threadIdx.x; idx < TILE * 32; idx += blockDim.x) {
            int nn = idx >> 5;
            int u  = idx & 31;
            int gn = tileBase + nn;
            if (gn < N)
                *(uint2*)&accS[nn * ROWH + u * 4] =
                    __ldg((const uint2*)(acc + (size_t)gn * LC) + u);
        }
        __syncthreads();

        {
            const int m  = threadIdx.x >> 6;
            const int ln = threadIdx.x & 63;
            if (tileBase + ln < N) {
                __half* seg = &accS[ln * ROWH + m * C];
                u64 yp[16];
#pragma unroll
                for (int i = 0; i < 16; i++) yp[i] = 0ULL;
#pragma unroll
                for (int j = 0; j < C; j++) {
                    float aj = __half2float(seg[j]);
                    u64 a2 = pack2(aj, aj);
                    const ulonglong2* wr = (const ulonglong2*)&KTs[(m * C + j) * C];
#pragma unroll
                    for (int c4 = 0; c4 < 8; c4++) {
                        ulonglong2 w = wr[c4];
                        yp[2 * c4 + 0] = fma2(a2, w.x, yp[2 * c4 + 0]);
                        yp[2 * c4 + 1] = fma2(a2, w.y, yp[2 * c4 + 1]);
                    }
                }
#pragma unroll
                for (int i = 0; i < 16; i++) {
                    float x, y;
                    unpack2(yp[i], x, y);
                    *(__half2*)(seg + 2 * i) = __float22half2_rn(make_float2(-x, -y));
                }
            }
        }
        __syncthreads();

#pragma unroll 1
        for (int k = 0; k < 8; k++) {
            const int idx = warp * 8 + k;
            const int n = tileBase + idx;
            if (n >= N) continue;
            const __half* rowp = &accS[idx * ROWH];
            float Y0 = __half2float(rowp[0 * C + lane]);
            float Y1 = __half2float(rowp[1 * C + lane]);
            float Y2 = __half2float(rowp[2 * C + lane]);
            float Y3 = __half2float(rowp[3 * C + lane]) + __ldg(X + (size_t)n * C + lane);

            const float s12 = 0.70710678118654752f;
            const float s23 = 0.81649658092772603f;
            const float s34 = 0.86602540378443865f;
            const float s45 = 0.89442719099991588f;
            float t0 = s12 * Y0;
            float t1 = s23 * (s12 * t0 + Y1);
            float t2 = s34 * (s23 * t1 + Y2);
            float t3 = s45 * (s34 * t2 + Y3);
            float w3 = s45 * t3;
            float w2 = s34 * (s34 * w3 + t2);
            float w1 = s23 * (s23 * w2 + t1);
            float w0 = s12 * (s12 * w1 + t0);

            const size_t base = (size_t)n * C + lane;
            Zout[0 * NC + base] = w0;
            Zout[1 * NC + base] = w1;
            Zout[2 * NC + base] = w2;
            Zout[3 * NC + base] = w3;
            if (lastOut) lastOut[base] = w3;
        }
    }
}

// ---------------------------------------------------------------------------
extern "C" void kernel_launch(void* const* d_in, const int* in_sizes, int n_in,
                              void* d_out, int out_size)
{
    const float* X  = (const float*)d_in[0];
    const float* f  = (const float*)d_in[1];
    const int*   ei = (const int*)d_in[2];
    const float* ew = (const float*)d_in[3];
    const float* K  = (const float*)d_in[4];
    const float* Kf = (const float*)d_in[5];

    const int N = in_sizes[0] / C;
    const int E = in_sizes[3];

    __half *dZ, *acc; float *Zb, *KT; uint2* rec; int* cnt;
    cudaGetSymbolAddress((void**)&dZ,  g_dZ);
    cudaGetSymbolAddress((void**)&acc, g_acc);
    cudaGetSymbolAddress((void**)&Zb,  g_Z);
    cudaGetSymbolAddress((void**)&KT,  g_KT);
    cudaGetSymbolAddress((void**)&rec, g_rec);
    cudaGetSymbolAddress((void**)&cnt, g_cnt);

    const size_t NC = (size_t)N * C;
    float* out = (float*)d_out;
    float* Zfinal;
    float* lastPtr;
    if ((size_t)out_size >= (size_t)(LAYERS + 1) * NC) {
        lastPtr = out;            // Z[-1] first
        Zfinal  = out + NC;       // then full Z
    } else if ((size_t)out_size >= (size_t)LAYERS * NC) {
        Zfinal  = out;
        lastPtr = nullptr;
    } else {
        Zfinal  = Zb;
        lastPtr = out;
    }

    const int edgeBlks = (E + 255) / 256;
    scatter_kt_kernel<<<edgeBlks + 16, 256>>>(ei, ew, cnt, rec, K, KT, E, edgeBlks);

    dim3 nodeGrid((N + 511) / 512, LAYERS);
    const int gatherBlocks = 888;                 // 6 per SM, 8 warps each
    const int mvtriBlocks  = 592;                 // 4 per SM, grid-stride tiles

    for (int it = 0; it < NFIX; it++) {
        node_forward_kernel<<<nodeGrid, 256>>>(Zb, f, Kf, K, dZ, N, it > 0 ? 1 : 0);
        edge_gather_kernel<<<gatherBlocks, 256>>>(dZ, rec, cnt, acc, N);
        const bool last = (it == NFIX - 1);
        mvtri_kernel<<<mvtriBlocks, 256>>>(acc, KT, X,
                                           last ? Zfinal : Zb,
                                           last ? lastPtr : nullptr,
                                           last ? cnt : nullptr,
                                           N);
    }
}

// round 13
// speedup vs baseline: 1.1285x; 1.0067x over previous
#include <cuda_runtime.h>
#include <cuda_fp16.h>
#include <math.h>

#define C 32
#define LAYERS 4
#define NFIX 2
#define MAXN 100000
#define MAXE 1600000
#define LC (LAYERS * C)   // 128
#define CAP 96            // per-node edge bucket capacity (deg ~ Poisson(16))
#define TILE 64           // nodes per mvtri tile
#define ROWH 40           // accS (m,node)-row stride in halves: 80B = 5 quads (odd -> conflict-free)

typedef unsigned long long u64;

// ---------------- device scratch (no runtime allocation allowed) -----------
// g_cnt starts zero (static init); every kernel_launch call leaves it zeroed
// (last mvtri re-zeros it), so scatter can histogram without a zeroing launch.
__device__ __align__(256) __half g_dZ[(size_t)MAXN * LC];        // [N][L][C] fp16
__device__ __align__(256) __half g_acc[(size_t)MAXN * LC];       // [N][L][C] fp16
__device__ __align__(256) float  g_Z[(size_t)LAYERS * MAXN * C]; // [L][N][C]
__device__ __align__(16)  float  g_KT[LAYERS * C * C];           // [m][j][c]
__device__ __align__(16)  uint2  g_rec[(size_t)MAXN * CAP];      // (t, w fp32)
__device__ int g_cnt[MAXN];

// ---------------- helpers ---------------------------------------------------
__device__ __forceinline__ float silu_f(float x) {
    float t;
    asm("tanh.approx.f32 %0, %1;" : "=f"(t) : "f"(0.5f * x));
    float hx = 0.5f * x;
    return fmaf(hx, t, hx);
}
__device__ __forceinline__ u64 pack2(float a, float b) {
    u64 r; asm("mov.b64 %0, {%1, %2};" : "=l"(r) : "f"(a), "f"(b)); return r;
}
__device__ __forceinline__ void unpack2(u64 v, float& a, float& b) {
    asm("mov.b64 {%0, %1}, %2;" : "=f"(a), "=f"(b) : "l"(v));
}
__device__ __forceinline__ u64 fma2(u64 a, u64 b, u64 c) {
    u64 d; asm("fma.rn.f32x2 %0, %1, %2, %3;" : "=l"(d) : "l"(a), "l"(b), "l"(c));
    return d;
}
__device__ __forceinline__ u64 add2(u64 a, u64 b) {
    u64 d; asm("add.rn.f32x2 %0, %1, %2;" : "=l"(d) : "l"(a), "l"(b));
    return d;
}
__device__ __forceinline__ __half2 htanh2(__half2 x) {
    unsigned r, xi = *(unsigned*)&x;
    asm("tanh.approx.f16x2 %0, %1;" : "=r"(r) : "r"(xi));
    return *(__half2*)&r;
}

// ---------------- setup: scatter (+ folded KT transpose) --------------------
__global__ void scatter_kt_kernel(const int* __restrict__ ei,
                                  const float* __restrict__ ew,
                                  int* cnt, uint2* rec,
                                  const float* __restrict__ K, float* __restrict__ KT,
                                  int E, int edgeBlks) {
    if ((int)blockIdx.x >= edgeBlks) {
        int i = (blockIdx.x - edgeBlks) * 256 + threadIdx.x;
        if (i < LAYERS * C * C) {
            int m = i >> 10;
            int c = (i >> 5) & 31;
            int j = i & 31;
            KT[m * C * C + j * C + c] = K[i];
        }
        return;
    }
    int e = blockIdx.x * 256 + threadIdx.x;
    if (e >= E) return;
    int s = __ldg(ei + e);
    int t = __ldg(ei + E + e);
    float w = __ldg(ew + e);
    int p = atomicAdd(&cnt[s], 1);
    if (p < CAP) rec[(size_t)s * CAP + p] = make_uint2((unsigned)t, __float_as_uint(w));
}

// ---------------------------------------------------------------------------
// Node forward (R10/R12 version, measured 57.7us): 2 nodes/thread, 128-reg cap.
// ---------------------------------------------------------------------------
__global__ __launch_bounds__(256, 2) void node_forward_kernel(
        const float* __restrict__ Z,
        const float* __restrict__ f,
        const float* __restrict__ Kf,
        const float* __restrict__ K,
        __half* __restrict__ dZ,
        int N, int useZ)
{
    __shared__ __align__(16) float Kfs[2 * C * C];   // 8 KB
    __shared__ __align__(16) float Ks[C * C];        // 4 KB
    const int l = blockIdx.y;
    {
        const float4* Kfl = (const float4*)(Kf + (size_t)l * 2 * C * C);
        const float4* Kl  = (const float4*)(K  + (size_t)l * C * C);
        float4* s0 = (float4*)Kfs;
        float4* s1 = (float4*)Ks;
        for (int i = threadIdx.x; i < 2 * C * C / 4; i += blockDim.x) s0[i] = Kfl[i];
        for (int i = threadIdx.x; i < C * C / 4;     i += blockDim.x) s1[i] = Kl[i];
    }
    __syncthreads();

    const int n0 = blockIdx.x * 512 + threadIdx.x;
    const int n1 = n0 + 256;
    if (n0 >= N) return;
    const bool v1 = (n1 < N);

    u64 hp0[16], hp1[16];
#pragma unroll
    for (int i = 0; i < 16; i++) { hp0[i] = 0ULL; hp1[i] = 0ULL; }

    if (useZ) {
        const float4* z0r = (const float4*)(Z + ((size_t)l * N + n0) * C);
        const float4* z1r = (const float4*)(Z + ((size_t)l * N + n1) * C);
#pragma unroll
        for (int k4 = 0; k4 < 8; k4++) {
            float4 a = z0r[k4];
            float4 b = v1 ? z1r[k4] : make_float4(0.f, 0.f, 0.f, 0.f);
            float as[4] = {a.x, a.y, a.z, a.w};
            float bs[4] = {b.x, b.y, b.z, b.w};
#pragma unroll
            for (int kk = 0; kk < 4; kk++) {
                u64 s0 = pack2(as[kk], as[kk]);
                u64 s1 = pack2(bs[kk], bs[kk]);
                const ulonglong2* wr = (const ulonglong2*)&Kfs[(k4 * 4 + kk) * C];
#pragma unroll
                for (int c4 = 0; c4 < 8; c4++) {
                    ulonglong2 w = wr[c4];
                    hp0[2 * c4 + 0] = fma2(s0, w.x, hp0[2 * c4 + 0]);
                    hp0[2 * c4 + 1] = fma2(s0, w.y, hp0[2 * c4 + 1]);
                    hp1[2 * c4 + 0] = fma2(s1, w.x, hp1[2 * c4 + 0]);
                    hp1[2 * c4 + 1] = fma2(s1, w.y, hp1[2 * c4 + 1]);
                }
            }
        }
    }
    {
        const float4* f0r = (const float4*)(f + (size_t)n0 * C);
        const float4* f1r = (const float4*)(f + (size_t)n1 * C);
#pragma unroll
        for (int k4 = 0; k4 < 8; k4++) {
            float4 a = f0r[k4];
            float4 b = v1 ? f1r[k4] : make_float4(0.f, 0.f, 0.f, 0.f);
            float as[4] = {a.x, a.y, a.z, a.w};
            float bs[4] = {b.x, b.y, b.z, b.w};
#pragma unroll
            for (int kk = 0; kk < 4; kk++) {
                u64 s0 = pack2(as[kk], as[kk]);
                u64 s1 = pack2(bs[kk], bs[kk]);
                const ulonglong2* wr = (const ulonglong2*)&Kfs[(C + k4 * 4 + kk) * C];
#pragma unroll
                for (int c4 = 0; c4 < 8; c4++) {
                    ulonglong2 w = wr[c4];
                    hp0[2 * c4 + 0] = fma2(s0, w.x, hp0[2 * c4 + 0]);
                    hp0[2 * c4 + 1] = fma2(s0, w.y, hp0[2 * c4 + 1]);
                    hp1[2 * c4 + 0] = fma2(s1, w.x, hp1[2 * c4 + 0]);
                    hp1[2 * c4 + 1] = fma2(s1, w.y, hp1[2 * c4 + 1]);
                }
            }
        }
    }

    float h0[C], h1[C];
#pragma unroll
    for (int i = 0; i < 16; i++) {
        unpack2(hp0[i], h0[2 * i], h0[2 * i + 1]);
        unpack2(hp1[i], h1[2 * i], h1[2 * i + 1]);
    }
#pragma unroll
    for (int c = 0; c < C; c++) { h0[c] = silu_f(h0[c]); h1[c] = silu_f(h1[c]); }

    __half* dz0 = dZ + ((size_t)n0 * LAYERS + l) * C;
    __half* dz1 = dZ + ((size_t)n1 * LAYERS + l) * C;
#pragma unroll
    for (int hf = 0; hf < 2; hf++) {
        u64 dp0[8], dp1[8];
#pragma unroll
        for (int i = 0; i < 8; i++) { dp0[i] = 0ULL; dp1[i] = 0ULL; }
#pragma unroll
        for (int k = 0; k < C; k++) {
            u64 s0 = pack2(h0[k], h0[k]);
            u64 s1 = pack2(h1[k], h1[k]);
            const ulonglong2* wr = (const ulonglong2*)&Ks[k * C + hf * 16];
#pragma unroll
            for (int c4 = 0; c4 < 4; c4++) {
                ulonglong2 w = wr[c4];
                dp0[2 * c4 + 0] = fma2(s0, w.x, dp0[2 * c4 + 0]);
                dp0[2 * c4 + 1] = fma2(s0, w.y, dp0[2 * c4 + 1]);
                dp1[2 * c4 + 0] = fma2(s1, w.x, dp1[2 * c4 + 0]);
                dp1[2 * c4 + 1] = fma2(s1, w.y, dp1[2 * c4 + 1]);
            }
        }
        union { __half2 h2[8]; uint4 u[2]; } p0, p1;
#pragma unroll
        for (int i = 0; i < 8; i++) {
            float x, y;
            unpack2(dp0[i], x, y);
            p0.h2[i] = __float22half2_rn(make_float2(x, y));
            unpack2(dp1[i], x, y);
            p1.h2[i] = __float22half2_rn(make_float2(x, y));
        }
        ((uint4*)dz0)[hf * 2 + 0] = p0.u[0];
        ((uint4*)dz0)[hf * 2 + 1] = p0.u[1];
        if (v1) {
            ((uint4*)dz1)[hf * 2 + 0] = p1.u[0];
            ((uint4*)dz1)[hf * 2 + 1] = p1.u[1];
        }
    }
}

// ---------------------------------------------------------------------------
// Edge gather (R10/R12 version): 2 nodes/warp (16 lanes each, uint4/lane),
// per-half deg loop, fp16x2 silu, f32x2 accumulate.
// ---------------------------------------------------------------------------
__device__ __forceinline__ void edge_accum4(uint4 zb,
                                            __half2 a0, __half2 a1, __half2 a2, __half2 a3,
                                            __half2 wh, u64* acc)
{
    __half2 b0 = *(__half2*)&zb.x;
    __half2 b1 = *(__half2*)&zb.y;
    __half2 b2 = *(__half2*)&zb.z;
    __half2 b3 = *(__half2*)&zb.w;
    __half2 hx0 = __hmul2(wh, __hsub2(a0, b0));
    __half2 hx1 = __hmul2(wh, __hsub2(a1, b1));
    __half2 hx2 = __hmul2(wh, __hsub2(a2, b2));
    __half2 hx3 = __hmul2(wh, __hsub2(a3, b3));
    __half2 t0 = htanh2(hx0);
    __half2 t1 = htanh2(hx1);
    __half2 t2 = htanh2(hx2);
    __half2 t3 = htanh2(hx3);
    __half2 g0 = __hfma2(hx0, t0, hx0);
    __half2 g1 = __hfma2(hx1, t1, hx1);
    __half2 g2 = __hfma2(hx2, t2, hx2);
    __half2 g3 = __hfma2(hx3, t3, hx3);
    float2 f0 = __half22float2(g0);
    float2 f1 = __half22float2(g1);
    float2 f2 = __half22float2(g2);
    float2 f3 = __half22float2(g3);
    acc[0] = add2(acc[0], pack2(f0.x, f0.y));
    acc[1] = add2(acc[1], pack2(f1.x, f1.y));
    acc[2] = add2(acc[2], pack2(f2.x, f2.y));
    acc[3] = add2(acc[3], pack2(f3.x, f3.y));
}

__global__ __launch_bounds__(256, 6) void edge_gather_kernel(
        const __half* __restrict__ dZ,
        const uint2* __restrict__ rec,
        const int* __restrict__ cnt,
        __half* __restrict__ acc,
        int N)
{
    const int lane = threadIdx.x & 31;
    const int warp = threadIdx.x >> 5;
    const int half = lane >> 4;
    const int sub  = lane & 15;
    const int gwarp = blockIdx.x * 8 + warp;
    const int nwarps = gridDim.x * 8;

    for (int nb = gwarp * 2; nb < N; nb += nwarps * 2) {
        const int n = nb + half;
        const bool valid = (n < N);
        const int nc = valid ? n : (N - 1);

        uint4 za = __ldg((const uint4*)(dZ + (size_t)nc * LC) + sub);
        __half2 a0 = *(__half2*)&za.x;
        __half2 a1 = *(__half2*)&za.y;
        __half2 a2 = *(__half2*)&za.z;
        __half2 a3 = *(__half2*)&za.w;

        u64 accv[4] = {0ULL, 0ULL, 0ULL, 0ULL};
        int deg = valid ? __ldg(cnt + nc) : 0;
        if (deg > CAP) deg = CAP;
        const uint2* row = rec + (size_t)nc * CAP;

        int p = 0;
        for (; p + 4 <= deg; p += 4) {
            uint2 r0 = __ldg(row + p + 0);
            uint2 r1 = __ldg(row + p + 1);
            uint2 r2 = __ldg(row + p + 2);
            uint2 r3 = __ldg(row + p + 3);
            uint4 z0 = __ldg((const uint4*)(dZ + (size_t)r0.x * LC) + sub);
            uint4 z1 = __ldg((const uint4*)(dZ + (size_t)r1.x * LC) + sub);
            uint4 z2 = __ldg((const uint4*)(dZ + (size_t)r2.x * LC) + sub);
            uint4 z3 = __ldg((const uint4*)(dZ + (size_t)r3.x * LC) + sub);
            edge_accum4(z0, a0, a1, a2, a3, __float2half2_rn(0.5f * __uint_as_float(r0.y)), accv);
            edge_accum4(z1, a0, a1, a2, a3, __float2half2_rn(0.5f * __uint_as_float(r1.y)), accv);
            edge_accum4(z2, a0, a1, a2, a3, __float2half2_rn(0.5f * __uint_as_float(r2.y)), accv);
            edge_accum4(z3, a0, a1, a2, a3, __float2half2_rn(0.5f * __uint_as_float(r3.y)), accv);
        }
        for (; p < deg; p++) {
            uint2 r0 = __ldg(row + p);
            uint4 z0 = __ldg((const uint4*)(dZ + (size_t)r0.x * LC) + sub);
            edge_accum4(z0, a0, a1, a2, a3, __float2half2_rn(0.5f * __uint_as_float(r0.y)), accv);
        }

        if (valid) {
            float x, y;
            uint4 packed;
            unpack2(accv[0], x, y);
            *(__half2*)&packed.x = __float22half2_rn(make_float2(x, y));
            unpack2(accv[1], x, y);
            *(__half2*)&packed.y = __float22half2_rn(make_float2(x, y));
            unpack2(accv[2], x, y);
            *(__half2*)&packed.z = __float22half2_rn(make_float2(x, y));
            unpack2(accv[3], x, y);
            *(__half2*)&packed.w = __float22half2_rn(make_float2(x, y));
            *(uint4*)(acc + (size_t)n * LC + sub * 8) = packed;
        }
    }
}

// ---------------------------------------------------------------------------
// mvtri: grid-stride over 64-node tiles. accS layout [m][node][ROWH=40 halves]
// (odd quad stride -> conflict-free LDS.128). Matvec thread-per-(node,m):
// seg preloaded into 16 half2 regs (4 LDS.128), j-loop from registers,
// writeback 4 LDS.128. KT loaded once per block. Tridiag warp-per-node.
// Last invocation also re-zeros cnt.
// ---------------------------------------------------------------------------
__global__ __launch_bounds__(256, 3) void mvtri_kernel(
        const __half* __restrict__ acc,
        const float* __restrict__ KTg,
        const float* __restrict__ X,
        float* __restrict__ Zout,
        float* __restrict__ lastOut,
        int* cntZero,
        int N)
{
    __shared__ __align__(16) float KTs[LAYERS * C * C];        // 16 KB
    __shared__ __align__(16) __half accS[LAYERS * TILE * ROWH]; // 20 KB

    if (cntZero) {
        for (int i = blockIdx.x * 256 + threadIdx.x; i < N; i += gridDim.x * 256)
            cntZero[i] = 0;
    }

    // KT loaded once per block (coalesced)
    {
        const float4* src = (const float4*)KTg;
        float4* dst = (float4*)KTs;
        for (int i = threadIdx.x; i < LAYERS * C * C / 4; i += blockDim.x)
            dst[i] = src[i];
    }

    const int numTiles = (N + TILE - 1) / TILE;
    const int lane = threadIdx.x & 31;
    const int warp = threadIdx.x >> 5;
    const int m  = threadIdx.x >> 6;      // warp-uniform
    const int ln = threadIdx.x & 63;
    const size_t NC = (size_t)N * C;

    for (int tile = blockIdx.x; tile < numTiles; tile += gridDim.x) {
        const int tileBase = tile * TILE;

        __syncthreads();   // KT ready (first iter) / accS free (later iters)

        // load acc tile: global [n][m*32+c] -> smem [(m*TILE+nn)*ROWH + c]
        for (int idx = threadIdx.x; idx < TILE * 16; idx += blockDim.x) {
            int nn = idx >> 4;
            int u  = idx & 15;            // uint4 (8 halves) index in 128-half row
            int mm = u >> 2;
            int c8 = (u & 3) * 8;
            int gn = tileBase + nn;
            if (gn < N)
                *(uint4*)&accS[(mm * TILE + nn) * ROWH + c8] =
                    __ldg((const uint4*)(acc + (size_t)gn * LC) + u);
        }
        __syncthreads();

        // ---- matvec: thread per (node, m) ----
        if (tileBase + ln < N) {
            __half* seg = &accS[(m * TILE + ln) * ROWH];
            uint4 s0 = *(const uint4*)(seg + 0);
            uint4 s1 = *(const uint4*)(seg + 8);
            uint4 s2 = *(const uint4*)(seg + 16);
            uint4 s3 = *(const uint4*)(seg + 24);
            unsigned hw[16] = {s0.x, s0.y, s0.z, s0.w,
                               s1.x, s1.y, s1.z, s1.w,
                               s2.x, s2.y, s2.z, s2.w,
                               s3.x, s3.y, s3.z, s3.w};
            u64 yp[16];
#pragma unroll
            for (int i = 0; i < 16; i++) yp[i] = 0ULL;
#pragma unroll
            for (int j = 0; j < C; j++) {
                __half2 hj = *(__half2*)&hw[j >> 1];
                float aj = (j & 1) ? __high2float(hj) : __low2float(hj);
                u64 a2 = pack2(aj, aj);
                const ulonglong2* wr = (const ulonglong2*)&KTs[(m * C + j) * C];
#pragma unroll
                for (int c4 = 0; c4 < 8; c4++) {
                    ulonglong2 w = wr[c4];
                    yp[2 * c4 + 0] = fma2(a2, w.x, yp[2 * c4 + 0]);
                    yp[2 * c4 + 1] = fma2(a2, w.y, yp[2 * c4 + 1]);
                }
            }
            // write back Y = -y as 4 x LDS.128
#pragma unroll
            for (int q = 0; q < 4; q++) {
                uint4 o;
                float x, y;
                unpack2(yp[4 * q + 0], x, y);
                *(__half2*)&o.x = __float22half2_rn(make_float2(-x, -y));
                unpack2(yp[4 * q + 1], x, y);
                *(__half2*)&o.y = __float22half2_rn(make_float2(-x, -y));
                unpack2(yp[4 * q + 2], x, y);
                *(__half2*)&o.z = __float22half2_rn(make_float2(-x, -y));
                unpack2(yp[4 * q + 3], x, y);
                *(__half2*)&o.w = __float22half2_rn(make_float2(-x, -y));
                *(uint4*)(seg + 8 * q) = o;
            }
        }
        __syncthreads();

        // ---- tridiag: warp per node ----
#pragma unroll 1
        for (int k = 0; k < 8; k++) {
            const int idx = warp * 8 + k;
            const int n = tileBase + idx;
            if (n >= N) continue;
            float Y0 = __half2float(accS[(0 * TILE + idx) * ROWH + lane]);
            float Y1 = __half2float(accS[(1 * TILE + idx) * ROWH + lane]);
            float Y2 = __half2float(accS[(2 * TILE + idx) * ROWH + lane]);
            float Y3 = __half2float(accS[(3 * TILE + idx) * ROWH + lane])
                       + __ldg(X + (size_t)n * C + lane);

            const float s12 = 0.70710678118654752f;
            const float s23 = 0.81649658092772603f;
            const float s34 = 0.86602540378443865f;
            const float s45 = 0.89442719099991588f;
            float t0 = s12 * Y0;
            float t1 = s23 * (s12 * t0 + Y1);
            float t2 = s34 * (s23 * t1 + Y2);
            float t3 = s45 * (s34 * t2 + Y3);
            float w3 = s45 * t3;
            float w2 = s34 * (s34 * w3 + t2);
            float w1 = s23 * (s23 * w2 + t1);
            float w0 = s12 * (s12 * w1 + t0);

            const size_t base = (size_t)n * C + lane;
            Zout[0 * NC + base] = w0;
            Zout[1 * NC + base] = w1;
            Zout[2 * NC + base] = w2;
            Zout[3 * NC + base] = w3;
            if (lastOut) lastOut[base] = w3;
        }
    }
}

// ---------------------------------------------------------------------------
extern "C" void kernel_launch(void* const* d_in, const int* in_sizes, int n_in,
                              void* d_out, int out_size)
{
    const float* X  = (const float*)d_in[0];
    const float* f  = (const float*)d_in[1];
    const int*   ei = (const int*)d_in[2];
    const float* ew = (const float*)d_in[3];
    const float* K  = (const float*)d_in[4];
    const float* Kf = (const float*)d_in[5];

    const int N = in_sizes[0] / C;
    const int E = in_sizes[3];

    __half *dZ, *acc; float *Zb, *KT; uint2* rec; int* cnt;
    cudaGetSymbolAddress((void**)&dZ,  g_dZ);
    cudaGetSymbolAddress((void**)&acc, g_acc);
    cudaGetSymbolAddress((void**)&Zb,  g_Z);
    cudaGetSymbolAddress((void**)&KT,  g_KT);
    cudaGetSymbolAddress((void**)&rec, g_rec);
    cudaGetSymbolAddress((void**)&cnt, g_cnt);

    const size_t NC = (size_t)N * C;
    float* out = (float*)d_out;
    float* Zfinal;
    float* lastPtr;
    if ((size_t)out_size >= (size_t)(LAYERS + 1) * NC) {
        lastPtr = out;            // Z[-1] first
        Zfinal  = out + NC;       // then full Z
    } else if ((size_t)out_size >= (size_t)LAYERS * NC) {
        Zfinal  = out;
        lastPtr = nullptr;
    } else {
        Zfinal  = Zb;
        lastPtr = out;
    }

    const int edgeBlks = (E + 255) / 256;
    scatter_kt_kernel<<<edgeBlks + 16, 256>>>(ei, ew, cnt, rec, K, KT, E, edgeBlks);

    dim3 nodeGrid((N + 511) / 512, LAYERS);
    const int gatherBlocks = 888;                 // 6 per SM, 8 warps each
    const int mvtriBlocks  = 444;                 // 3 per SM, grid-stride tiles

    for (int it = 0; it < NFIX; it++) {
        node_forward_kernel<<<nodeGrid, 256>>>(Zb, f, Kf, K, dZ, N, it > 0 ? 1 : 0);
        edge_gather_kernel<<<gatherBlocks, 256>>>(dZ, rec, cnt, acc, N);
        const bool last = (it == NFIX - 1);
        mvtri_kernel<<<mvtriBlocks, 256>>>(acc, KT, X,
                                           last ? Zfinal : Zb,
                                           last ? lastPtr : nullptr,
                                           last ? cnt : nullptr,
                                           N);
    }
}